// round 14
// baseline (speedup 1.0000x reference)
#include <cuda_runtime.h>
#include <cuda_fp16.h>
#include <cstdint>
#include <math.h>

#define DIM 128
#define MAXN 50000
#define MAXP 25000
#define MAXE 600000
#define TILE 4096
#define MAXTILES 16

// ---------------- device scratch ----------------
__device__ __half g_th16[(size_t)MAXN * DIM];
__device__ __half g_ph16[(size_t)MAXP * DIM];
__device__ __half g_pout16[(size_t)MAXP * DIM];
__device__ __half g_tout16[(size_t)MAXN * DIM];
__device__ __half g_S16[(size_t)MAXN * DIM];
__device__ __half g_W216[3 * 128 * 256];
__device__ float  g_bc[3 * DIM];
// cnt (3*MAXN) + tilesum sentinels (3*MAXTILES), zeroed by ONE memset
__device__ int    g_cntbuf[3 * MAXN + 3 * MAXTILES];
__device__ int    g_rowptr[3][MAXN + 1];
__device__ int    g_rank[3][MAXE];
__device__ int    g_srclist[3][MAXE];

#define CNT(s)  (g_cntbuf + (s) * MAXN)
#define TSUM(s) (g_cntbuf + 3 * MAXN + (s) * MAXTILES)

__device__ __forceinline__ void mma_f16(float* c, const uint32_t* a, uint32_t b0, uint32_t b1) {
    asm volatile(
        "mma.sync.aligned.m16n8k16.row.col.f32.f16.f16.f32 "
        "{%0,%1,%2,%3}, {%4,%5,%6,%7}, {%8,%9}, {%0,%1,%2,%3};"
        : "+f"(c[0]), "+f"(c[1]), "+f"(c[2]), "+f"(c[3])
        : "r"(a[0]), "r"(a[1]), "r"(a[2]), "r"(a[3]), "r"(b0), "r"(b1));
}

__device__ __forceinline__ void cp16(uint32_t smem_addr, const void* gptr) {
    asm volatile("cp.async.ca.shared.global [%0], [%1], 16;"
                 :: "r"(smem_addr), "l"(gptr) : "memory");
}
#define CP_COMMIT() asm volatile("cp.async.commit_group;" ::: "memory")
#define CP_WAIT(n)  asm volatile("cp.async.wait_group %0;" :: "n"(n) : "memory")

// ---------------- K1: count + rank capture (3 stages, one launch) ----------------
__global__ void count_kernel(const int* __restrict__ d0, int E0,
                             const int* __restrict__ d1, int E1,
                             const int* __restrict__ d2, int E2)
{
    int s = blockIdx.y;
    const int* dst = (s == 0) ? d0 : (s == 1) ? d1 : d2;
    int E = (s == 0) ? E0 : (s == 1) ? E1 : E2;
    int e = (blockIdx.x * blockDim.x + threadIdx.x) * 4;
    if (e >= E) return;
    int* cnt = CNT(s);
    int* rank = g_rank[s];
    if (e + 3 < E) {
        int4 v = *(const int4*)(dst + e);
        int4 r;
        r.x = atomicAdd(&cnt[v.x], 1);
        r.y = atomicAdd(&cnt[v.y], 1);
        r.z = atomicAdd(&cnt[v.z], 1);
        r.w = atomicAdd(&cnt[v.w], 1);
        *(int4*)(rank + e) = r;
    } else {
        for (int q = 0; q < 4 && e + q < E; q++)
            rank[e + q] = atomicAdd(&cnt[dst[e + q]], 1);
    }
}

// ---------------- K2: fused scan (tile sum + lookback + tile scan) ----------------
__global__ void scan_fused_kernel(int N0, int N1, int N2)
{
    __shared__ int wsum[8];
    __shared__ int wexcl[8];
    __shared__ int tile_off_sh;
    int s = blockIdx.y;
    int N = (s == 0) ? N0 : (s == 1) ? N1 : N2;
    int bx = blockIdx.x;
    int base = bx * TILE;
    if (base >= N) return;
    int* cnt = CNT(s);
    int* rowptr = g_rowptr[s];
    int t = threadIdx.x;
    int lane = t & 31, wid = t >> 5;
    int ntiles = (N + TILE - 1) / TILE;

    int local = 0;
    #pragma unroll
    for (int q = 0; q < 4; q++) {
        int i = base + (t + q * 256) * 4;
        if (i + 3 < N) {
            int4 v = *(const int4*)(cnt + i);
            local += v.x + v.y + v.z + v.w;
        } else {
            for (int j = 0; j < 4; j++)
                if (i + j < N) local += cnt[i + j];
        }
    }
    #pragma unroll
    for (int off = 16; off > 0; off >>= 1)
        local += __shfl_down_sync(0xFFFFFFFF, local, off);
    if (lane == 0) wsum[wid] = local;
    __syncthreads();
    if (t == 0) {
        int tot = 0;
        #pragma unroll
        for (int w = 0; w < 8; w++) tot += wsum[w];
        atomicExch(&TSUM(s)[bx], tot + 1);
        int off = 0;
        for (int i = 0; i < bx; i++) {
            int v;
            do { v = *(volatile int*)&TSUM(s)[i]; } while (v == 0);
            off += v - 1;
        }
        tile_off_sh = off;
        if (bx == ntiles - 1) rowptr[N] = off + tot;
    }
    __syncthreads();

    int e0 = base + t * 16;
    int c[16];
    #pragma unroll
    for (int q = 0; q < 16; q++) {
        int i = e0 + q;
        c[q] = (i < N) ? cnt[i] : 0;
    }
    int tot = 0;
    #pragma unroll
    for (int q = 0; q < 16; q++) tot += c[q];

    int x = tot;
    #pragma unroll
    for (int off = 1; off < 32; off <<= 1) {
        int y = __shfl_up_sync(0xFFFFFFFF, x, off);
        if (lane >= off) x += y;
    }
    int texcl = x - tot;
    if (lane == 31) wsum[wid] = x;
    __syncthreads();
    if (t == 0) {
        int run = 0;
        #pragma unroll
        for (int w = 0; w < 8; w++) { wexcl[w] = run; run += wsum[w]; }
    }
    __syncthreads();

    int pre = tile_off_sh + wexcl[wid] + texcl;
    #pragma unroll
    for (int q = 0; q < 16; q++) {
        int i = e0 + q;
        if (i < N) rowptr[i] = pre;
        pre += c[q];
    }
}

// ---- fill body ----
__device__ __forceinline__ void fill_body(int s, const int* __restrict__ src,
                                          const int* __restrict__ dst, int E, int bl, int t)
{
    int e = (bl * 256 + t) * 4;
    if (e >= E) return;
    const int* rowptr = g_rowptr[s];
    const int* rank = g_rank[s];
    int* srclist = g_srclist[s];
    if (e + 3 < E) {
        int4 d = *(const int4*)(dst + e);
        int4 sv = *(const int4*)(src + e);
        int4 r = *(const int4*)(rank + e);
        srclist[rowptr[d.x] + r.x] = sv.x;
        srclist[rowptr[d.y] + r.y] = sv.y;
        srclist[rowptr[d.z] + r.z] = sv.z;
        srclist[rowptr[d.w] + r.w] = sv.w;
    } else {
        for (int q = 0; q < 4 && e + q < E; q++)
            srclist[rowptr[dst[e + q]] + rank[e + q]] = src[e + q];
    }
}

// ---------------- K3: convert + fill(all 3 stages) + weight prep ----------------
__global__ __launch_bounds__(256) void mid_kernel(
    const float* __restrict__ th, int ntv, const float* __restrict__ ph, int npv, int BC,
    const int* __restrict__ s0, const int* __restrict__ d0, int E0, int BF0,
    const int* __restrict__ s1, const int* __restrict__ d1, int E1, int BF1,
    const int* __restrict__ s2, const int* __restrict__ d2, int E2, int BF2,
    const float* __restrict__ W_t2p, const float* __restrict__ b_t2p, const float* __restrict__ W_pu,
    const float* __restrict__ W_p2t, const float* __restrict__ b_p2t, const float* __restrict__ W_tup,
    const float* __restrict__ W_t2t, const float* __restrict__ b_t2t, const float* __restrict__ W_tut)
{
    int b = blockIdx.x;
    int t = threadIdx.x;

    if (b < BC) {
        int i = b * 256 + t;
        int tot = ntv + npv;
        if (i >= tot) return;
        if (i < ntv) {
            float4 v = *(const float4*)(th + (size_t)i * 4);
            __half2* d = (__half2*)(g_th16 + (size_t)i * 4);
            d[0] = __floats2half2_rn(v.x, v.y);
            d[1] = __floats2half2_rn(v.z, v.w);
        } else {
            int j = i - ntv;
            float4 v = *(const float4*)(ph + (size_t)j * 4);
            __half2* d = (__half2*)(g_ph16 + (size_t)j * 4);
            d[0] = __floats2half2_rn(v.x, v.y);
            d[1] = __floats2half2_rn(v.z, v.w);
        }
        return;
    }
    b -= BC;
    if (b < BF0) { fill_body(0, s0, d0, E0, b, t); return; }
    b -= BF0;
    if (b < BF1) { fill_body(1, s1, d1, E1, b, t); return; }
    b -= BF1;
    if (b < BF2) { fill_body(2, s2, d2, E2, b, t); return; }
    b -= BF2;
    {
        int unit = b * 2 + (t >> 7);
        if (unit >= 384) return;
        int s = unit >> 7;
        int j = unit & 127;
        int k = t & 127;

        const float *Wm, *Wu, *bm;
        if (s == 0)      { Wm = W_t2p; Wu = W_pu;  bm = b_t2p; }
        else if (s == 1) { Wm = W_p2t; Wu = W_tup; bm = b_p2t; }
        else             { Wm = W_t2t; Wu = W_tut; bm = b_t2t; }

        __half* W2s = g_W216 + (size_t)s * 128 * 256;
        W2s[j * 256 + k] = __float2half_rn(Wu[j * 256 + k]);

        float acc = 0.f;
        #pragma unroll 8
        for (int l = 0; l < 128; l++)
            acc = fmaf(Wu[j * 256 + 128 + l], Wm[l * DIM + k], acc);
        W2s[j * 256 + 128 + k] = __float2half_rn(acc);

        if (k == 0) {
            float a = 0.f;
            for (int l = 0; l < 128; l++)
                a = fmaf(Wu[j * 256 + 128 + l], bm[l], a);
            g_bc[s * DIM + j] = a;
        }
    }
}

// ---- agg: warp per row, half-warp per edge, uint4 loads ----
__global__ void agg_kernel(int stage, const __half* __restrict__ H, int N)
{
    int w = (blockIdx.x * blockDim.x + threadIdx.x) >> 5;
    int lane = threadIdx.x & 31;
    if (w >= N) return;
    const int* rowptr = g_rowptr[stage];
    const int* srclist = g_srclist[stage];
    int s0 = rowptr[w];
    int s1 = rowptr[w + 1];
    int half = lane >> 4;
    int cl = lane & 15;
    int colb = cl * 8;

    float a[8];
    #pragma unroll
    for (int q = 0; q < 8; q++) a[q] = 0.f;

    int i = s0;
    for (; i + 4 <= s1; i += 4) {
        int j0 = srclist[i + half];
        int j1 = srclist[i + 2 + half];
        uint4 v0 = *(const uint4*)(H + (size_t)j0 * DIM + colb);
        uint4 v1 = *(const uint4*)(H + (size_t)j1 * DIM + colb);
        float2 f;
        f = __half22float2(*(__half2*)&v0.x); a[0] += f.x; a[1] += f.y;
        f = __half22float2(*(__half2*)&v0.y); a[2] += f.x; a[3] += f.y;
        f = __half22float2(*(__half2*)&v0.z); a[4] += f.x; a[5] += f.y;
        f = __half22float2(*(__half2*)&v0.w); a[6] += f.x; a[7] += f.y;
        f = __half22float2(*(__half2*)&v1.x); a[0] += f.x; a[1] += f.y;
        f = __half22float2(*(__half2*)&v1.y); a[2] += f.x; a[3] += f.y;
        f = __half22float2(*(__half2*)&v1.z); a[4] += f.x; a[5] += f.y;
        f = __half22float2(*(__half2*)&v1.w); a[6] += f.x; a[7] += f.y;
    }
    for (; i + 2 <= s1; i += 2) {
        int j = srclist[i + half];
        uint4 v = *(const uint4*)(H + (size_t)j * DIM + colb);
        float2 f;
        f = __half22float2(*(__half2*)&v.x); a[0] += f.x; a[1] += f.y;
        f = __half22float2(*(__half2*)&v.y); a[2] += f.x; a[3] += f.y;
        f = __half22float2(*(__half2*)&v.z); a[4] += f.x; a[5] += f.y;
        f = __half22float2(*(__half2*)&v.w); a[6] += f.x; a[7] += f.y;
    }
    if (i < s1 && half == 0) {
        int j = srclist[i];
        uint4 v = *(const uint4*)(H + (size_t)j * DIM + colb);
        float2 f;
        f = __half22float2(*(__half2*)&v.x); a[0] += f.x; a[1] += f.y;
        f = __half22float2(*(__half2*)&v.y); a[2] += f.x; a[3] += f.y;
        f = __half22float2(*(__half2*)&v.z); a[4] += f.x; a[5] += f.y;
        f = __half22float2(*(__half2*)&v.w); a[6] += f.x; a[7] += f.y;
    }
    __syncwarp();
    #pragma unroll
    for (int q = 0; q < 8; q++)
        a[q] += __shfl_xor_sync(0xFFFFFFFF, a[q], 16);

    if (half == 0) {
        int cn = s1 - s0;
        float inv = (cn > 0) ? (1.f / (float)cn) : 0.f;
        uint4 o;
        *(__half2*)&o.x = __floats2half2_rn(a[0] * inv, a[1] * inv);
        *(__half2*)&o.y = __floats2half2_rn(a[2] * inv, a[3] * inv);
        *(__half2*)&o.z = __floats2half2_rn(a[4] * inv, a[5] * inv);
        *(__half2*)&o.w = __floats2half2_rn(a[6] * inv, a[7] * inv);
        *(uint4*)(g_S16 + (size_t)w * DIM + colb) = o;
    }
}

// ---------------- fp16 mma.sync update GEMM, cp.async double-buffered ----------------
#define XSTRH 72
#define BUF_E (128 * XSTRH)
#define SMEM_UPD (4 * BUF_E * 2 + 1536)

__global__ __launch_bounds__(256) void update_mma_kernel(
    int stage, const __half* __restrict__ H,
    const float* __restrict__ bu,
    float* __restrict__ out32, __half* __restrict__ out16, int N)
{
    extern __shared__ __align__(16) char dsm[];
    __half* Asb = (__half*)dsm;
    __half* Bsb = (__half*)(dsm + 2 * BUF_E * 2);
    float*  ms  = (float*)(dsm + 4 * BUF_E * 2);
    float*  bus = ms + 128;
    float*  bcs = bus + 128;

    int t = threadIdx.x;
    int r0 = blockIdx.x * 128;
    const __half* W2 = g_W216 + (size_t)stage * 128 * 256;

    if (t < 128) {
        int row = r0 + t;
        int c = (row < N) ? CNT(stage)[row] : 0;
        ms[t]  = (c > 0) ? 1.f : 0.f;
        bus[t] = bu[t];
        bcs[t] = g_bc[stage * DIM + t];
    }

    int lane = t & 31;
    int wid  = t >> 5;
    int g  = lane >> 2;
    int t4 = lane & 3;
    int wm = wid >> 1;
    int wn = wid & 1;

    int rl0 = t >> 3;
    int c8  = t & 7;
    int rowc[4];
    #pragma unroll
    for (int q = 0; q < 4; q++) {
        int row = r0 + rl0 + q * 32;
        rowc[q] = (row < N) ? row : (N - 1);
    }

    auto issue = [&](int kc, int buf) {
        __half* Ab = Asb + buf * BUF_E;
        __half* Bb = Bsb + buf * BUF_E;
        int kg = kc * 64 + c8 * 8;
        const __half* baseH = (kg < 128) ? H + kg : g_S16 + (kg - 128);
        #pragma unroll
        for (int q = 0; q < 4; q++) {
            int rl = rl0 + q * 32;
            cp16((uint32_t)__cvta_generic_to_shared(&Ab[rl * XSTRH + c8 * 8]),
                 baseH + (size_t)rowc[q] * DIM);
            cp16((uint32_t)__cvta_generic_to_shared(&Bb[rl * XSTRH + c8 * 8]),
                 W2 + (size_t)rl * 256 + kg);
        }
        CP_COMMIT();
    };

    issue(0, 0);
    issue(1, 1);

    float acc[2][8][4];
    #pragma unroll
    for (int mt = 0; mt < 2; mt++)
        #pragma unroll
        for (int nt = 0; nt < 8; nt++)
            #pragma unroll
            for (int i = 0; i < 4; i++) acc[mt][nt][i] = 0.f;

    #pragma unroll
    for (int kc = 0; kc < 4; kc++) {
        if (kc < 3) { CP_WAIT(1); } else { CP_WAIT(0); }
        __syncthreads();

        const __half* As = Asb + (kc & 1) * BUF_E;
        const __half* Bs = Bsb + (kc & 1) * BUF_E;

        #pragma unroll
        for (int ks = 0; ks < 4; ks++) {
            int kb = ks * 16;
            uint32_t a[2][4];
            #pragma unroll
            for (int mt = 0; mt < 2; mt++) {
                int rbase = (wm * 32 + mt * 16 + g) * XSTRH + kb + t4 * 2;
                a[mt][0] = *(const uint32_t*)&As[rbase];
                a[mt][1] = *(const uint32_t*)&As[rbase + 8 * XSTRH];
                a[mt][2] = *(const uint32_t*)&As[rbase + 8];
                a[mt][3] = *(const uint32_t*)&As[rbase + 8 * XSTRH + 8];
            }
            #pragma unroll
            for (int nt = 0; nt < 8; nt++) {
                int bbase = (wn * 64 + nt * 8 + g) * XSTRH + kb + t4 * 2;
                uint32_t b0 = *(const uint32_t*)&Bs[bbase];
                uint32_t b1 = *(const uint32_t*)&Bs[bbase + 8];
                mma_f16(acc[0][nt], a[0], b0, b1);
                mma_f16(acc[1][nt], a[1], b0, b1);
            }
        }
        __syncthreads();
        if (kc + 2 < 4) issue(kc + 2, kc & 1);
    }

    #pragma unroll
    for (int mt = 0; mt < 2; mt++) {
        int rl1 = wm * 32 + mt * 16 + g;
        int row1 = r0 + rl1;
        int row2 = row1 + 8;
        float m1 = ms[rl1], m2 = ms[rl1 + 8];
        #pragma unroll
        for (int nt = 0; nt < 8; nt++) {
            int col = wn * 64 + nt * 8 + t4 * 2;
            float bu0 = bus[col], bu1 = bus[col + 1];
            float bc0 = bcs[col], bc1 = bcs[col + 1];
            float2 o1, o2;
            o1.x = fmaxf(acc[mt][nt][0] + bu0 + m1 * bc0, 0.f);
            o1.y = fmaxf(acc[mt][nt][1] + bu1 + m1 * bc1, 0.f);
            o2.x = fmaxf(acc[mt][nt][2] + bu0 + m2 * bc0, 0.f);
            o2.y = fmaxf(acc[mt][nt][3] + bu1 + m2 * bc1, 0.f);
            if (row1 < N) {
                if (out32) *(float2*)(out32 + (size_t)row1 * DIM + col) = o1;
                if (out16) *(__half2*)(out16 + (size_t)row1 * DIM + col) = __floats2half2_rn(o1.x, o1.y);
            }
            if (row2 < N) {
                if (out32) *(float2*)(out32 + (size_t)row2 * DIM + col) = o2;
                if (out16) *(__half2*)(out16 + (size_t)row2 * DIM + col) = __floats2half2_rn(o2.x, o2.y);
            }
        }
    }
}

// ---------------- host orchestration ----------------
extern "C" void kernel_launch(void* const* d_in, const int* in_sizes, int n_in,
                              void* d_out, int out_size)
{
    const float* tile_h    = (const float*)d_in[0];
    const float* piece_h   = (const float*)d_in[1];
    const int*   tile_src  = (const int*)d_in[2];
    const int*   piece_dst = (const int*)d_in[3];
    const int*   piece_src = (const int*)d_in[4];
    const int*   tile_dst  = (const int*)d_in[5];
    const int*   t_src     = (const int*)d_in[6];
    const int*   t_dst     = (const int*)d_in[7];

    int NT  = in_sizes[0] / DIM;
    int NP  = in_sizes[1] / DIM;
    int EPT = in_sizes[2];
    int ETT = in_sizes[6];

    float* out       = (float*)d_out;
    float* out_tile  = out;
    float* out_piece = out + (size_t)NT * DIM;

    __half *th16_p, *ph16_p, *pout16_p, *tout16_p;
    int *cntbuf_p;
    cudaGetSymbolAddress((void**)&th16_p, g_th16);
    cudaGetSymbolAddress((void**)&ph16_p, g_ph16);
    cudaGetSymbolAddress((void**)&pout16_p, g_pout16);
    cudaGetSymbolAddress((void**)&tout16_p, g_tout16);
    cudaGetSymbolAddress((void**)&cntbuf_p, g_cntbuf);

    cudaFuncSetAttribute(update_mma_kernel,
                         cudaFuncAttributeMaxDynamicSharedMemorySize, SMEM_UPD);

    cudaMemsetAsync(cntbuf_p, 0, (3 * (size_t)MAXN + 3 * MAXTILES) * sizeof(int));

    // K1: count + rank (edge lists only)
    int maxE = ETT > EPT ? ETT : EPT;
    dim3 cg((maxE + 1023) / 1024, 3);
    count_kernel<<<cg, 256>>>(piece_dst, EPT, tile_dst, EPT, t_dst, ETT);

    // K2: fused scan (all 3 stages)
    int maxN = NT > NP ? NT : NP;
    dim3 sg((maxN + TILE - 1) / TILE, 3);
    scan_fused_kernel<<<sg, 256>>>(NP, NT, NT);

    // K3: convert + all fills + weight prep (all mutually independent)
    int ntv = NT * 32, npv = NP * 32;
    int BC  = (ntv + npv + 255) / 256;
    int BF0 = (EPT + 1023) / 1024;
    int BF1 = (EPT + 1023) / 1024;
    int BF2 = (ETT + 1023) / 1024;
    int BP  = 192;
    mid_kernel<<<BC + BF0 + BF1 + BF2 + BP, 256>>>(
        tile_h, ntv, piece_h, npv, BC,
        tile_src, piece_dst, EPT, BF0,
        piece_src, tile_dst, EPT, BF1,
        t_src, t_dst, ETT, BF2,
        (const float*)d_in[8],  (const float*)d_in[9],  (const float*)d_in[10],
        (const float*)d_in[12], (const float*)d_in[13], (const float*)d_in[14],
        (const float*)d_in[16], (const float*)d_in[17], (const float*)d_in[18]);

    // Stage 1: tile -> piece
    agg_kernel<<<(NP + 7) / 8, 256>>>(0, th16_p, NP);
    update_mma_kernel<<<(NP + 127) / 128, 256, SMEM_UPD>>>(
        0, ph16_p, (const float*)d_in[11], out_piece, pout16_p, NP);

    // Stage 2: piece -> tile
    agg_kernel<<<(NT + 7) / 8, 256>>>(1, pout16_p, NT);
    update_mma_kernel<<<(NT + 127) / 128, 256, SMEM_UPD>>>(
        1, th16_p, (const float*)d_in[15], nullptr, tout16_p, NT);

    // Stage 3: tile -> tile
    agg_kernel<<<(NT + 7) / 8, 256>>>(2, tout16_p, NT);
    update_mma_kernel<<<(NT + 127) / 128, 256, SMEM_UPD>>>(
        2, tout16_p, (const float*)d_in[19], out_tile, nullptr, NT);
}

// round 15
// speedup vs baseline: 1.0269x; 1.0269x over previous
#include <cuda_runtime.h>
#include <cuda_fp16.h>
#include <cstdint>
#include <math.h>

#define DIM 128
#define MAXN 50000
#define MAXP 25000
#define MAXE 600000
#define TILE 4096
#define MAXTILES 16

// ---------------- device scratch ----------------
__device__ __half g_th16[(size_t)MAXN * DIM];
__device__ __half g_ph16[(size_t)MAXP * DIM];
__device__ __half g_pout16[(size_t)MAXP * DIM];
__device__ __half g_tout16[(size_t)MAXN * DIM];
__device__ __half g_S16[(size_t)MAXN * DIM];
__device__ __half g_W216[3 * 128 * 256];
__device__ float  g_bc[3 * DIM];
__device__ int    g_cnt[3][MAXN];
__device__ int    g_rowptr[3][MAXN + 1];
__device__ int    g_rank[3][MAXE];
__device__ int    g_srclist[3][MAXE];
__device__ int    g_tilesum[3][MAXTILES];

__device__ __forceinline__ void mma_f16(float* c, const uint32_t* a, uint32_t b0, uint32_t b1) {
    asm volatile(
        "mma.sync.aligned.m16n8k16.row.col.f32.f16.f16.f32 "
        "{%0,%1,%2,%3}, {%4,%5,%6,%7}, {%8,%9}, {%0,%1,%2,%3};"
        : "+f"(c[0]), "+f"(c[1]), "+f"(c[2]), "+f"(c[3])
        : "r"(a[0]), "r"(a[1]), "r"(a[2]), "r"(a[3]), "r"(b0), "r"(b1));
}

__device__ __forceinline__ void cp16(uint32_t smem_addr, const void* gptr) {
    asm volatile("cp.async.ca.shared.global [%0], [%1], 16;"
                 :: "r"(smem_addr), "l"(gptr) : "memory");
}
#define CP_COMMIT() asm volatile("cp.async.commit_group;" ::: "memory")
#define CP_WAIT(n)  asm volatile("cp.async.wait_group %0;" :: "n"(n) : "memory")

// ---------------- fused: convert + count(+rank) + weight prep ----------------
__global__ __launch_bounds__(256) void fused_front_kernel(
    const float* __restrict__ th, int ntv, const float* __restrict__ ph, int npv,
    const int* __restrict__ d0, int E0, const int* __restrict__ d1, int E1,
    const int* __restrict__ d2, int E2,
    int BC, int BE0, int BE1, int BE2,
    const float* __restrict__ W_t2p, const float* __restrict__ b_t2p, const float* __restrict__ W_pu,
    const float* __restrict__ W_p2t, const float* __restrict__ b_p2t, const float* __restrict__ W_tup,
    const float* __restrict__ W_t2t, const float* __restrict__ b_t2t, const float* __restrict__ W_tut)
{
    int b = blockIdx.x;
    int t = threadIdx.x;

    if (b < BC) {
        int i = b * 256 + t;
        int tot = ntv + npv;
        if (i >= tot) return;
        if (i < ntv) {
            float4 v = *(const float4*)(th + (size_t)i * 4);
            __half2* d = (__half2*)(g_th16 + (size_t)i * 4);
            d[0] = __floats2half2_rn(v.x, v.y);
            d[1] = __floats2half2_rn(v.z, v.w);
        } else {
            int j = i - ntv;
            float4 v = *(const float4*)(ph + (size_t)j * 4);
            __half2* d = (__half2*)(g_ph16 + (size_t)j * 4);
            d[0] = __floats2half2_rn(v.x, v.y);
            d[1] = __floats2half2_rn(v.z, v.w);
        }
        return;
    }
    b -= BC;
    if (b < BE0 + BE1 + BE2) {
        int s, bl;
        const int* dst;
        int E;
        if (b < BE0)            { s = 0; bl = b;             dst = d0; E = E0; }
        else if (b < BE0 + BE1) { s = 1; bl = b - BE0;       dst = d1; E = E1; }
        else                    { s = 2; bl = b - BE0 - BE1; dst = d2; E = E2; }
        int e = (bl * 256 + t) * 4;
        int* cnt = g_cnt[s];
        int* rank = g_rank[s];
        if (e + 3 < E) {
            int4 v = *(const int4*)(dst + e);
            int4 r;
            r.x = atomicAdd(&cnt[v.x], 1);
            r.y = atomicAdd(&cnt[v.y], 1);
            r.z = atomicAdd(&cnt[v.z], 1);
            r.w = atomicAdd(&cnt[v.w], 1);
            *(int4*)(rank + e) = r;
        } else {
            for (int q = 0; q < 4 && e + q < E; q++)
                rank[e + q] = atomicAdd(&cnt[dst[e + q]], 1);
        }
        return;
    }
    b -= BE0 + BE1 + BE2;
    {
        int unit = b * 2 + (t >> 7);
        if (unit >= 384) return;
        int s = unit >> 7;
        int j = unit & 127;
        int k = t & 127;

        const float *Wm, *Wu, *bm;
        if (s == 0)      { Wm = W_t2p; Wu = W_pu;  bm = b_t2p; }
        else if (s == 1) { Wm = W_p2t; Wu = W_tup; bm = b_p2t; }
        else             { Wm = W_t2t; Wu = W_tut; bm = b_t2t; }

        __half* W2s = g_W216 + (size_t)s * 128 * 256;
        W2s[j * 256 + k] = __float2half_rn(Wu[j * 256 + k]);

        float acc = 0.f;
        #pragma unroll 8
        for (int l = 0; l < 128; l++)
            acc = fmaf(Wu[j * 256 + 128 + l], Wm[l * DIM + k], acc);
        W2s[j * 256 + 128 + k] = __float2half_rn(acc);

        if (k == 0) {
            float a = 0.f;
            for (int l = 0; l < 128; l++)
                a = fmaf(Wu[j * 256 + 128 + l], bm[l], a);
            g_bc[s * DIM + j] = a;
        }
    }
}

// ---- scan phase A: per-tile sums ----
__global__ void tilesum_kernel(int N0, int N1, int N2)
{
    __shared__ int wsum[8];
    int s = blockIdx.y;
    int N = (s == 0) ? N0 : (s == 1) ? N1 : N2;
    int base = blockIdx.x * TILE;
    if (base >= N) return;
    const int* cnt = g_cnt[s];
    int t = threadIdx.x;
    int local = 0;
    #pragma unroll
    for (int q = 0; q < 4; q++) {
        int i = base + (t + q * 256) * 4;
        if (i + 3 < N) {
            int4 v = *(const int4*)(cnt + i);
            local += v.x + v.y + v.z + v.w;
        } else {
            for (int j = 0; j < 4; j++)
                if (i + j < N) local += cnt[i + j];
        }
    }
    #pragma unroll
    for (int off = 16; off > 0; off >>= 1)
        local += __shfl_down_sync(0xFFFFFFFF, local, off);
    if ((t & 31) == 0) wsum[t >> 5] = local;
    __syncthreads();
    if (t == 0) {
        int tot = 0;
        #pragma unroll
        for (int w = 0; w < 8; w++) tot += wsum[w];
        g_tilesum[s][blockIdx.x] = tot;
    }
}

// ---- scan phase B: per-tile block scan ----
__global__ void scanC_kernel(int N0, int N1, int N2)
{
    __shared__ int wsum[8];
    __shared__ int wexcl[8];
    __shared__ int tile_off;
    int s = blockIdx.y;
    int N = (s == 0) ? N0 : (s == 1) ? N1 : N2;
    int base = blockIdx.x * TILE;
    if (base >= N) return;
    const int* cnt = g_cnt[s];
    int* rowptr = g_rowptr[s];
    int t = threadIdx.x;
    int lane = t & 31, wid = t >> 5;
    int ntiles = (N + TILE - 1) / TILE;

    if (t == 0) {
        int off = 0;
        for (int i = 0; i < (int)blockIdx.x; i++) off += g_tilesum[s][i];
        tile_off = off;
        if ((int)blockIdx.x == ntiles - 1)
            rowptr[N] = off + g_tilesum[s][blockIdx.x];
    }

    int e0 = base + t * 16;
    int c[16];
    #pragma unroll
    for (int q = 0; q < 16; q++) {
        int i = e0 + q;
        c[q] = (i < N) ? cnt[i] : 0;
    }
    int tot = 0;
    #pragma unroll
    for (int q = 0; q < 16; q++) tot += c[q];

    int x = tot;
    #pragma unroll
    for (int off = 1; off < 32; off <<= 1) {
        int y = __shfl_up_sync(0xFFFFFFFF, x, off);
        if (lane >= off) x += y;
    }
    int texcl = x - tot;
    if (lane == 31) wsum[wid] = x;
    __syncthreads();
    if (t == 0) {
        int run = 0;
        #pragma unroll
        for (int w = 0; w < 8; w++) { wexcl[w] = run; run += wsum[w]; }
    }
    __syncthreads();

    int pre = tile_off + wexcl[wid] + texcl;
    #pragma unroll
    for (int q = 0; q < 16; q++) {
        int i = e0 + q;
        if (i < N) rowptr[i] = pre;
        pre += c[q];
    }
}

// ---- fill: atomic-free, pos = rowptr[dst] + rank ----
__global__ void fill3_kernel(const int* __restrict__ s0, const int* __restrict__ d0, int E0,
                             const int* __restrict__ s1, const int* __restrict__ d1, int E1,
                             const int* __restrict__ s2, const int* __restrict__ d2, int E2)
{
    int s = blockIdx.y;
    const int* src = (s == 0) ? s0 : (s == 1) ? s1 : s2;
    const int* dst = (s == 0) ? d0 : (s == 1) ? d1 : d2;
    int E = (s == 0) ? E0 : (s == 1) ? E1 : E2;
    int e = (blockIdx.x * blockDim.x + threadIdx.x) * 4;
    const int* rowptr = g_rowptr[s];
    const int* rank = g_rank[s];
    int* srclist = g_srclist[s];
    if (e + 3 < E) {
        int4 d = *(const int4*)(dst + e);
        int4 sv = *(const int4*)(src + e);
        int4 r = *(const int4*)(rank + e);
        srclist[rowptr[d.x] + r.x] = sv.x;
        srclist[rowptr[d.y] + r.y] = sv.y;
        srclist[rowptr[d.z] + r.z] = sv.z;
        srclist[rowptr[d.w] + r.w] = sv.w;
    } else {
        for (int q = 0; q < 4 && e + q < E; q++)
            srclist[rowptr[dst[e + q]] + rank[e + q]] = src[e + q];
    }
}

// ---------------- aggregation: warp per row, fp16 pair-combine ----------------
// Each half-warp handles a PAIR of edges per iteration; the two edges are
// combined with packed HADD2 before fp32 conversion — 40% fewer math instrs.
__global__ void agg_kernel(int stage, const __half* __restrict__ H, int N)
{
    int w = (blockIdx.x * blockDim.x + threadIdx.x) >> 5;
    int lane = threadIdx.x & 31;
    if (w >= N) return;
    const int* rowptr = g_rowptr[stage];
    const int* srclist = g_srclist[stage];
    int s0 = rowptr[w];
    int s1 = rowptr[w + 1];
    int half = lane >> 4;
    int cl = lane & 15;
    int colb = cl * 8;

    float a[8];
    #pragma unroll
    for (int q = 0; q < 8; q++) a[q] = 0.f;

    int i = s0;
    // main loop: 4 edges per iteration; each half-warp pair-combines 2 edges in fp16
    for (; i + 4 <= s1; i += 4) {
        int j0 = srclist[i + 2 * half];
        int j1 = srclist[i + 2 * half + 1];
        uint4 v0 = *(const uint4*)(H + (size_t)j0 * DIM + colb);
        uint4 v1 = *(const uint4*)(H + (size_t)j1 * DIM + colb);
        __half2 h;
        float2 f;
        h = __hadd2(*(__half2*)&v0.x, *(__half2*)&v1.x); f = __half22float2(h); a[0] += f.x; a[1] += f.y;
        h = __hadd2(*(__half2*)&v0.y, *(__half2*)&v1.y); f = __half22float2(h); a[2] += f.x; a[3] += f.y;
        h = __hadd2(*(__half2*)&v0.z, *(__half2*)&v1.z); f = __half22float2(h); a[4] += f.x; a[5] += f.y;
        h = __hadd2(*(__half2*)&v0.w, *(__half2*)&v1.w); f = __half22float2(h); a[6] += f.x; a[7] += f.y;
    }
    // remainder: 2-3 edges -> half-warp per edge
    for (; i + 2 <= s1; i += 2) {
        int j = srclist[i + half];
        uint4 v = *(const uint4*)(H + (size_t)j * DIM + colb);
        float2 f;
        f = __half22float2(*(__half2*)&v.x); a[0] += f.x; a[1] += f.y;
        f = __half22float2(*(__half2*)&v.y); a[2] += f.x; a[3] += f.y;
        f = __half22float2(*(__half2*)&v.z); a[4] += f.x; a[5] += f.y;
        f = __half22float2(*(__half2*)&v.w); a[6] += f.x; a[7] += f.y;
    }
    // final single edge (lanes 0-15 only)
    if (i < s1 && half == 0) {
        int j = srclist[i];
        uint4 v = *(const uint4*)(H + (size_t)j * DIM + colb);
        float2 f;
        f = __half22float2(*(__half2*)&v.x); a[0] += f.x; a[1] += f.y;
        f = __half22float2(*(__half2*)&v.y); a[2] += f.x; a[3] += f.y;
        f = __half22float2(*(__half2*)&v.z); a[4] += f.x; a[5] += f.y;
        f = __half22float2(*(__half2*)&v.w); a[6] += f.x; a[7] += f.y;
    }
    __syncwarp();
    #pragma unroll
    for (int q = 0; q < 8; q++)
        a[q] += __shfl_xor_sync(0xFFFFFFFF, a[q], 16);

    if (half == 0) {
        int cn = s1 - s0;
        float inv = (cn > 0) ? (1.f / (float)cn) : 0.f;
        uint4 o;
        *(__half2*)&o.x = __floats2half2_rn(a[0] * inv, a[1] * inv);
        *(__half2*)&o.y = __floats2half2_rn(a[2] * inv, a[3] * inv);
        *(__half2*)&o.z = __floats2half2_rn(a[4] * inv, a[5] * inv);
        *(__half2*)&o.w = __floats2half2_rn(a[6] * inv, a[7] * inv);
        *(uint4*)(g_S16 + (size_t)w * DIM + colb) = o;
    }
}

// ---------------- fp16 mma.sync update GEMM, cp.async double-buffered ----------------
#define XSTRH 72
#define BUF_E (128 * XSTRH)
#define SMEM_UPD (4 * BUF_E * 2 + 1536)

__global__ __launch_bounds__(256) void update_mma_kernel(
    int stage, const __half* __restrict__ H,
    const float* __restrict__ bu,
    float* __restrict__ out32, __half* __restrict__ out16, int N)
{
    extern __shared__ __align__(16) char dsm[];
    __half* Asb = (__half*)dsm;
    __half* Bsb = (__half*)(dsm + 2 * BUF_E * 2);
    float*  ms  = (float*)(dsm + 4 * BUF_E * 2);
    float*  bus = ms + 128;
    float*  bcs = bus + 128;

    int t = threadIdx.x;
    int r0 = blockIdx.x * 128;
    const __half* W2 = g_W216 + (size_t)stage * 128 * 256;

    if (t < 128) {
        int row = r0 + t;
        int c = (row < N) ? g_cnt[stage][row] : 0;
        ms[t]  = (c > 0) ? 1.f : 0.f;
        bus[t] = bu[t];
        bcs[t] = g_bc[stage * DIM + t];
    }

    int lane = t & 31;
    int wid  = t >> 5;
    int g  = lane >> 2;
    int t4 = lane & 3;
    int wm = wid >> 1;
    int wn = wid & 1;

    int rl0 = t >> 3;
    int c8  = t & 7;
    int rowc[4];
    #pragma unroll
    for (int q = 0; q < 4; q++) {
        int row = r0 + rl0 + q * 32;
        rowc[q] = (row < N) ? row : (N - 1);
    }

    auto issue = [&](int kc, int buf) {
        __half* Ab = Asb + buf * BUF_E;
        __half* Bb = Bsb + buf * BUF_E;
        int kg = kc * 64 + c8 * 8;
        const __half* baseH = (kg < 128) ? H + kg : g_S16 + (kg - 128);
        #pragma unroll
        for (int q = 0; q < 4; q++) {
            int rl = rl0 + q * 32;
            cp16((uint32_t)__cvta_generic_to_shared(&Ab[rl * XSTRH + c8 * 8]),
                 baseH + (size_t)rowc[q] * DIM);
            cp16((uint32_t)__cvta_generic_to_shared(&Bb[rl * XSTRH + c8 * 8]),
                 W2 + (size_t)rl * 256 + kg);
        }
        CP_COMMIT();
    };

    issue(0, 0);
    issue(1, 1);

    float acc[2][8][4];
    #pragma unroll
    for (int mt = 0; mt < 2; mt++)
        #pragma unroll
        for (int nt = 0; nt < 8; nt++)
            #pragma unroll
            for (int i = 0; i < 4; i++) acc[mt][nt][i] = 0.f;

    #pragma unroll
    for (int kc = 0; kc < 4; kc++) {
        if (kc < 3) { CP_WAIT(1); } else { CP_WAIT(0); }
        __syncthreads();

        const __half* As = Asb + (kc & 1) * BUF_E;
        const __half* Bs = Bsb + (kc & 1) * BUF_E;

        #pragma unroll
        for (int ks = 0; ks < 4; ks++) {
            int kb = ks * 16;
            uint32_t a[2][4];
            #pragma unroll
            for (int mt = 0; mt < 2; mt++) {
                int rbase = (wm * 32 + mt * 16 + g) * XSTRH + kb + t4 * 2;
                a[mt][0] = *(const uint32_t*)&As[rbase];
                a[mt][1] = *(const uint32_t*)&As[rbase + 8 * XSTRH];
                a[mt][2] = *(const uint32_t*)&As[rbase + 8];
                a[mt][3] = *(const uint32_t*)&As[rbase + 8 * XSTRH + 8];
            }
            #pragma unroll
            for (int nt = 0; nt < 8; nt++) {
                int bbase = (wn * 64 + nt * 8 + g) * XSTRH + kb + t4 * 2;
                uint32_t b0 = *(const uint32_t*)&Bs[bbase];
                uint32_t b1 = *(const uint32_t*)&Bs[bbase + 8];
                mma_f16(acc[0][nt], a[0], b0, b1);
                mma_f16(acc[1][nt], a[1], b0, b1);
            }
        }
        __syncthreads();
        if (kc + 2 < 4) issue(kc + 2, kc & 1);
    }

    #pragma unroll
    for (int mt = 0; mt < 2; mt++) {
        int rl1 = wm * 32 + mt * 16 + g;
        int row1 = r0 + rl1;
        int row2 = row1 + 8;
        float m1 = ms[rl1], m2 = ms[rl1 + 8];
        #pragma unroll
        for (int nt = 0; nt < 8; nt++) {
            int col = wn * 64 + nt * 8 + t4 * 2;
            float bu0 = bus[col], bu1 = bus[col + 1];
            float bc0 = bcs[col], bc1 = bcs[col + 1];
            float2 o1, o2;
            o1.x = fmaxf(acc[mt][nt][0] + bu0 + m1 * bc0, 0.f);
            o1.y = fmaxf(acc[mt][nt][1] + bu1 + m1 * bc1, 0.f);
            o2.x = fmaxf(acc[mt][nt][2] + bu0 + m2 * bc0, 0.f);
            o2.y = fmaxf(acc[mt][nt][3] + bu1 + m2 * bc1, 0.f);
            if (row1 < N) {
                if (out32) *(float2*)(out32 + (size_t)row1 * DIM + col) = o1;
                if (out16) *(__half2*)(out16 + (size_t)row1 * DIM + col) = __floats2half2_rn(o1.x, o1.y);
            }
            if (row2 < N) {
                if (out32) *(float2*)(out32 + (size_t)row2 * DIM + col) = o2;
                if (out16) *(__half2*)(out16 + (size_t)row2 * DIM + col) = __floats2half2_rn(o2.x, o2.y);
            }
        }
    }
}

// ---------------- host orchestration ----------------
extern "C" void kernel_launch(void* const* d_in, const int* in_sizes, int n_in,
                              void* d_out, int out_size)
{
    const float* tile_h    = (const float*)d_in[0];
    const float* piece_h   = (const float*)d_in[1];
    const int*   tile_src  = (const int*)d_in[2];
    const int*   piece_dst = (const int*)d_in[3];
    const int*   piece_src = (const int*)d_in[4];
    const int*   tile_dst  = (const int*)d_in[5];
    const int*   t_src     = (const int*)d_in[6];
    const int*   t_dst     = (const int*)d_in[7];

    int NT  = in_sizes[0] / DIM;
    int NP  = in_sizes[1] / DIM;
    int EPT = in_sizes[2];
    int ETT = in_sizes[6];

    float* out       = (float*)d_out;
    float* out_tile  = out;
    float* out_piece = out + (size_t)NT * DIM;

    __half *th16_p, *ph16_p, *pout16_p, *tout16_p;
    int *cnt_p;
    cudaGetSymbolAddress((void**)&th16_p, g_th16);
    cudaGetSymbolAddress((void**)&ph16_p, g_ph16);
    cudaGetSymbolAddress((void**)&pout16_p, g_pout16);
    cudaGetSymbolAddress((void**)&tout16_p, g_tout16);
    cudaGetSymbolAddress((void**)&cnt_p, g_cnt);

    cudaFuncSetAttribute(update_mma_kernel,
                         cudaFuncAttributeMaxDynamicSharedMemorySize, SMEM_UPD);

    cudaMemsetAsync(cnt_p, 0, 3 * (size_t)MAXN * sizeof(int));

    int ntv = NT * 32, npv = NP * 32;
    int BC  = (ntv + npv + 255) / 256;
    int BE0 = (EPT + 1023) / 1024;
    int BE1 = (EPT + 1023) / 1024;
    int BE2 = (ETT + 1023) / 1024;
    int BP  = 192;
    fused_front_kernel<<<BC + BE0 + BE1 + BE2 + BP, 256>>>(
        tile_h, ntv, piece_h, npv,
        piece_dst, EPT, tile_dst, EPT, t_dst, ETT,
        BC, BE0, BE1, BE2,
        (const float*)d_in[8],  (const float*)d_in[9],  (const float*)d_in[10],
        (const float*)d_in[12], (const float*)d_in[13], (const float*)d_in[14],
        (const float*)d_in[16], (const float*)d_in[17], (const float*)d_in[18]);

    int maxN = NT > NP ? NT : NP;
    dim3 sg((maxN + TILE - 1) / TILE, 3);
    tilesum_kernel<<<sg, 256>>>(NP, NT, NT);
    scanC_kernel<<<sg, 256>>>(NP, NT, NT);

    int maxE = ETT > EPT ? ETT : EPT;
    dim3 fg((maxE + 1023) / 1024, 3);
    fill3_kernel<<<fg, 256>>>(tile_src, piece_dst, EPT,
                              piece_src, tile_dst, EPT,
                              t_src, t_dst, ETT);

    // Stage 1: tile -> piece
    agg_kernel<<<(NP + 7) / 8, 256>>>(0, th16_p, NP);
    update_mma_kernel<<<(NP + 127) / 128, 256, SMEM_UPD>>>(
        0, ph16_p, (const float*)d_in[11], out_piece, pout16_p, NP);

    // Stage 2: piece -> tile
    agg_kernel<<<(NT + 7) / 8, 256>>>(1, pout16_p, NT);
    update_mma_kernel<<<(NT + 127) / 128, 256, SMEM_UPD>>>(
        1, th16_p, (const float*)d_in[15], nullptr, tout16_p, NT);

    // Stage 3: tile -> tile
    agg_kernel<<<(NT + 7) / 8, 256>>>(2, tout16_p, NT);
    update_mma_kernel<<<(NT + 127) / 128, 256, SMEM_UPD>>>(
        2, tout16_p, (const float*)d_in[19], out_tile, nullptr, NT);
}